// round 4
// baseline (speedup 1.0000x reference)
#include <cuda_runtime.h>
#include <math.h>

#define B_      4
#define T_      4096
#define HID_    768
#define H_      12
#define D_      64
#define BH_     48
#define NHASH_  2
#define NBUCK_  32
#define NBTOT_  64
#define TOTAL_  8192
#define NCH_    64
#define CL_     128
#define M_      (B_*T_)      // 16384
#define PADK    65

// ---------------- scratch (static device globals; no allocation) ----------------
__device__ float g_qk[BH_*T_*D_];            // [bh][t][d]  (shared q/k projection)
__device__ float g_v [BH_*T_*D_];
__device__ int   g_bucket[BH_*TOTAL_];       // bucket in [0,64) incl. hash offset
__device__ int   g_sidx[BH_*TOTAL_];         // sorted pos -> original flat index j
__device__ int   g_undo[BH_*TOTAL_];         // original j -> sorted pos
__device__ int   g_bbase[BH_*NBTOT_];        // per-bh exclusive bucket offsets
__device__ float g_so  [BH_*TOTAL_*D_];      // per sorted row attention output
__device__ float g_slog[BH_*TOTAL_];         // per sorted row logsumexp
__device__ float g_attn[M_*HID_];            // unsorted combined attn, [b*T+t][hid]
__device__ float g_tmp [M_*HID_];            // after W_to

// ---------------- generic fp32 SGEMM: C[M,768] = A[M,768] @ W[768,768]^T (+bias) ----------------
// INMODE:  0 = A param, 1 = g_attn, 2 = g_tmp
// OUTMODE: 0 = Cout row-major (+bias), 3 = g_tmp row-major (+bias),
//          1 = g_qk merged-head, 2 = g_v merged-head
template<int INMODE, int OUTMODE>
__global__ __launch_bounds__(256) void sgemm_kernel(const float* __restrict__ Ain,
                                                    const float* __restrict__ W,
                                                    const float* __restrict__ bias,
                                                    float* __restrict__ Cout)
{
    const float* A = (INMODE == 0) ? Ain : (INMODE == 1 ? (const float*)g_attn : (const float*)g_tmp);
    __shared__ float As[16][128];
    __shared__ float Ws[16][64];
    const int K = HID_;
    int bm = blockIdx.y * 128;
    int bn = blockIdx.x * 64;
    int tid = threadIdx.x;
    int tx = tid & 15, ty = tid >> 4;

    float acc[8][4];
#pragma unroll
    for (int i = 0; i < 8; i++)
#pragma unroll
        for (int j = 0; j < 4; j++) acc[i][j] = 0.f;

    for (int k0 = 0; k0 < K; k0 += 16) {
#pragma unroll
        for (int li = 0; li < 2; li++) {
            int i   = tid + li * 256;           // 0..511
            int row = i >> 2;
            int kq  = (i & 3) << 2;
            float4 av = *(const float4*)(A + (size_t)(bm + row) * K + k0 + kq);
            As[kq+0][row] = av.x; As[kq+1][row] = av.y;
            As[kq+2][row] = av.z; As[kq+3][row] = av.w;
        }
        {
            int row = tid >> 2;
            int kq  = (tid & 3) << 2;
            float4 wv = *(const float4*)(W + (size_t)(bn + row) * K + k0 + kq);
            Ws[kq+0][row] = wv.x; Ws[kq+1][row] = wv.y;
            Ws[kq+2][row] = wv.z; Ws[kq+3][row] = wv.w;
        }
        __syncthreads();
#pragma unroll
        for (int kk = 0; kk < 16; kk++) {
            float4 a0 = *(const float4*)&As[kk][ty*8];
            float4 a1 = *(const float4*)&As[kk][ty*8 + 4];
            float4 bv = *(const float4*)&Ws[kk][tx*4];
            float a[8] = {a0.x,a0.y,a0.z,a0.w,a1.x,a1.y,a1.z,a1.w};
            float b[4] = {bv.x,bv.y,bv.z,bv.w};
#pragma unroll
            for (int i = 0; i < 8; i++)
#pragma unroll
                for (int j = 0; j < 4; j++)
                    acc[i][j] = fmaf(a[i], b[j], acc[i][j]);
        }
        __syncthreads();
    }

    int col = bn + tx * 4;
    float b0 = 0.f, b1 = 0.f, b2 = 0.f, b3 = 0.f;
    if (OUTMODE == 0 || OUTMODE == 3) { b0 = bias[col]; b1 = bias[col+1]; b2 = bias[col+2]; b3 = bias[col+3]; }
#pragma unroll
    for (int i = 0; i < 8; i++) {
        int row = bm + ty * 8 + i;
        float4 o = make_float4(acc[i][0]+b0, acc[i][1]+b1, acc[i][2]+b2, acc[i][3]+b3);
        if (OUTMODE == 0) {
            *(float4*)(Cout + (size_t)row * HID_ + col) = o;
        } else if (OUTMODE == 3) {
            *(float4*)(g_tmp + (size_t)row * HID_ + col) = o;
        } else {
            int b = row >> 12, t = row & (T_-1);
            int h = col >> 6,  dd = col & 63;
            float* dst = (OUTMODE == 1) ? g_qk : g_v;
            *(float4*)(dst + ((size_t)(b * H_ + h) * T_ + t) * D_ + dd) = o;
        }
    }
}

// ---------------- LSH bucketing: warp per (bh, t) ----------------
__global__ __launch_bounds__(256) void bucket_kernel(const float* __restrict__ rot)
{
    __shared__ float srot[D_ * 32];   // rotations [d][hash*16+i], 2048 floats
    int tid = threadIdx.x;
    for (int i = tid; i < D_ * 32; i += 256) srot[i] = rot[i];
    __syncthreads();

    int lane = tid & 31;
    int wid  = tid >> 5;
    int row  = blockIdx.x * 8 + wid;      // 0 .. BH_*T_-1
    int bh   = row >> 12;
    int t    = row & (T_-1);

    const float* q = g_qk + ((size_t)bh * T_ + t) * D_;
    float q0 = q[lane], q1 = q[lane + 32];
    float r = 0.f;
#pragma unroll
    for (int d = 0; d < 32; d++)
        r = fmaf(__shfl_sync(0xffffffffu, q0, d), srot[d * 32 + lane], r);
#pragma unroll
    for (int d = 0; d < 32; d++)
        r = fmaf(__shfl_sync(0xffffffffu, q1, d), srot[(d + 32) * 32 + lane], r);

    // lane = hash*16 + i ; candidates: r at idx i, -r at idx i+16. argmax = first max.
    int i = lane & 15;
    float nr = -r;
    float v; int idx;
    if (r >= nr) { v = r;  idx = i; } else { v = nr; idx = i + 16; }
#pragma unroll
    for (int off = 8; off > 0; off >>= 1) {
        float ov = __shfl_down_sync(0xffffffffu, v,   off, 16);
        int   oi = __shfl_down_sync(0xffffffffu, idx, off, 16);
        if (ov > v || (ov == v && oi < idx)) { v = ov; idx = oi; }
    }
    if (i == 0) {
        int hash = lane >> 4;
        g_bucket[bh * TOTAL_ + hash * T_ + t] = idx + hash * NBUCK_;
    }
}

// ---------------- histogram + exclusive scan per bh ----------------
__global__ __launch_bounds__(256) void hist_kernel()
{
    __shared__ int h[NBTOT_];
    int bh = blockIdx.x;
    int tid = threadIdx.x;
    if (tid < NBTOT_) h[tid] = 0;
    __syncthreads();
    const int* bp = g_bucket + bh * TOTAL_;
    for (int j = tid; j < TOTAL_; j += 256) atomicAdd(&h[bp[j]], 1);
    __syncthreads();
    if (tid == 0) {
        int run = 0;
        for (int b = 0; b < NBTOT_; b++) { g_bbase[bh * NBTOT_ + b] = run; run += h[b]; }
    }
}

// ---------------- stable scatter: one block per (bucket, bh) ----------------
__global__ __launch_bounds__(256) void scatter_kernel()
{
    int bh  = blockIdx.y;
    int myb = blockIdx.x;
    int tid = threadIdx.x;
    const int* bp = g_bucket + bh * TOTAL_;
    int j0 = tid * 32;
    int cnt = 0;
    for (int k = 0; k < 32; k++) cnt += (bp[j0 + k] == myb);

    __shared__ int s[256];
    s[tid] = cnt;
    __syncthreads();
    for (int off = 1; off < 256; off <<= 1) {
        int v = (tid >= off) ? s[tid - off] : 0;
        __syncthreads();
        s[tid] += v;
        __syncthreads();
    }
    int pos = g_bbase[bh * NBTOT_ + myb] + s[tid] - cnt;
    for (int k = 0; k < 32; k++) {
        int j = j0 + k;
        if (bp[j] == myb) {
            g_sidx[bh * TOTAL_ + pos] = j;
            g_undo[bh * TOTAL_ + j]   = pos;
            pos++;
        }
    }
}

// ---------------- chunked LSH attention: one block per (chunk, bh) ----------------
constexpr int ATTN_SMEM_FLOATS = 128*PADK + 256*PADK + 256*PADK + 8*16*PADK;
constexpr int ATTN_SMEM_BYTES  = ATTN_SMEM_FLOATS*4 + (128+256+128+256)*4;

__global__ __launch_bounds__(256, 1) void attn_kernel(const float* __restrict__ mask)
{
    extern __shared__ float smem_f[];
    float* sq = smem_f;                 // [128][65]
    float* sk = sq + 128*PADK;          // [256][65] (normalized keys)
    float* sv = sk + 256*PADK;          // [256][65]
    float* sp = sv + 256*PADK;          // per-warp p tile [8][16][65]
    int*   tq = (int*)(sp + 8*16*PADK); // [128] query time positions
    int*   tk = tq + 128;               // [256] key time positions
    int*   mq = tk + 256;               // [128]
    int*   mk = mq + 128;               // [256]

    int c   = blockIdx.x;
    int bh  = blockIdx.y;
    int tid = threadIdx.x;
    int base = bh * TOTAL_;
    const float* mrow = mask + (bh / H_) * T_;

    if (tid < 128) {
        int si = g_sidx[base + c * CL_ + tid];
        int tp = si & (T_-1);
        tq[tid] = tp;
        mq[tid] = (mrow[tp] != 0.f);
    }
    {
        int j  = tid;
        int cp = (c + NCH_ - 1) & (NCH_ - 1);                    // look-one-back chunk
        int spos = (j < CL_) ? (c * CL_ + j) : (cp * CL_ + (j - CL_));
        int si = g_sidx[base + spos];
        int tp = si & (T_-1);
        tk[j] = tp;
        mk[j] = (mrow[tp] != 0.f);
    }
    __syncthreads();

    const float* qkb = g_qk + (size_t)bh * T_ * D_;
    const float* vb  = g_v  + (size_t)bh * T_ * D_;
    for (int idx = tid; idx < 128 * 64; idx += 256) {
        int r = idx >> 6, d = idx & 63;
        sq[r * PADK + d] = qkb[(size_t)tq[r] * D_ + d];
    }
    for (int idx = tid; idx < 256 * 64; idx += 256) {
        int r = idx >> 6, d = idx & 63;
        sk[r * PADK + d] = qkb[(size_t)tk[r] * D_ + d];
        sv[r * PADK + d] =  vb[(size_t)tk[r] * D_ + d];
    }
    __syncthreads();
    {   // normalize keys (thread per key row)
        int r = tid;
        float ss = 0.f;
#pragma unroll 8
        for (int d = 0; d < 64; d++) { float x = sk[r*PADK + d]; ss = fmaf(x, x, ss); }
        float inv = 1.f / fmaxf(sqrtf(ss), 1e-12f);
#pragma unroll 8
        for (int d = 0; d < 64; d++) sk[r*PADK + d] *= inv;
    }
    __syncthreads();

    int w = tid >> 5, lane = tid & 31;
    int rr = lane & 3, kk = lane >> 2;
    float* spw = sp + w * 16 * PADK;
    int rbase = w * 16 + rr;

    float m_[4], l_[4], oacc[4][8];
#pragma unroll
    for (int u = 0; u < 4; u++) {
        m_[u] = -INFINITY; l_[u] = 0.f;
#pragma unroll
        for (int v = 0; v < 8; v++) oacc[u][v] = 0.f;
    }
    int tqr[4], mqr[4];
#pragma unroll
    for (int u = 0; u < 4; u++) { tqr[u] = tq[rbase + 4*u]; mqr[u] = mq[rbase + 4*u]; }

    for (int tt = 0; tt < 4; tt++) {
        int jb = tt * 64;
        float dots[4][8];
#pragma unroll
        for (int u = 0; u < 4; u++)
#pragma unroll
            for (int s = 0; s < 8; s++) dots[u][s] = 0.f;

        for (int d = 0; d < 64; d++) {
            float qv[4];
#pragma unroll
            for (int u = 0; u < 4; u++) qv[u] = sq[(rbase + 4*u) * PADK + d];
#pragma unroll
            for (int s = 0; s < 8; s++) {
                float kv = sk[(jb + kk + 8*s) * PADK + d];
#pragma unroll
                for (int u = 0; u < 4; u++) dots[u][s] = fmaf(qv[u], kv, dots[u][s]);
            }
        }

        float tmax[4];
#pragma unroll
        for (int u = 0; u < 4; u++) {
            float mx = -INFINITY;
#pragma unroll
            for (int s = 0; s < 8; s++) {
                int j = jb + kk + 8*s;
                float val = dots[u][s] * 0.125f;
                if (!(mqr[u] && mk[j])) val = -1e9f;     // pad mask
                if (tqr[u] == tk[j])    val = -5e4f;     // self-attention mask
                dots[u][s] = val;
                mx = fmaxf(mx, val);
            }
            tmax[u] = mx;
        }
#pragma unroll
        for (int off = 4; off < 32; off <<= 1)
#pragma unroll
            for (int u = 0; u < 4; u++)
                tmax[u] = fmaxf(tmax[u], __shfl_xor_sync(0xffffffffu, tmax[u], off));

        float corr[4], lsum[4];
#pragma unroll
        for (int u = 0; u < 4; u++) {
            float mn = fmaxf(m_[u], tmax[u]);
            corr[u] = __expf(m_[u] - mn);
            m_[u] = mn;
            float sloc = 0.f;
#pragma unroll
            for (int s = 0; s < 8; s++) {
                float p = __expf(dots[u][s] - mn);
                dots[u][s] = p;
                sloc += p;
            }
            lsum[u] = sloc;
        }
#pragma unroll
        for (int off = 4; off < 32; off <<= 1)
#pragma unroll
            for (int u = 0; u < 4; u++)
                lsum[u] += __shfl_xor_sync(0xffffffffu, lsum[u], off);
#pragma unroll
        for (int u = 0; u < 4; u++) {
            l_[u] = l_[u] * corr[u] + lsum[u];
#pragma unroll
            for (int v = 0; v < 8; v++) oacc[u][v] *= corr[u];
#pragma unroll
            for (int s = 0; s < 8; s++) spw[(rr + 4*u) * PADK + kk + 8*s] = dots[u][s];
        }
        __syncwarp();

        for (int jl = 0; jl < 64; jl++) {
            float pv[4];
#pragma unroll
            for (int u = 0; u < 4; u++) pv[u] = spw[(rr + 4*u) * PADK + jl];
            float vvr[8];
#pragma unroll
            for (int v = 0; v < 8; v++) vvr[v] = sv[(jb + jl) * PADK + kk + 8*v];
#pragma unroll
            for (int u = 0; u < 4; u++)
#pragma unroll
                for (int v = 0; v < 8; v++)
                    oacc[u][v] = fmaf(pv[u], vvr[v], oacc[u][v]);
        }
        __syncwarp();
    }

#pragma unroll
    for (int u = 0; u < 4; u++) {
        int r  = rbase + 4*u;
        int gp = base + c * CL_ + r;
        float inv = 1.f / l_[u];
        if (kk == 0) g_slog[gp] = m_[u] + logf(l_[u]);
#pragma unroll
        for (int v = 0; v < 8; v++)
            g_so[(size_t)gp * D_ + kk + 8*v] = oacc[u][v] * inv;
    }
}

// ---------------- unsort + combine hash rounds ----------------
__global__ __launch_bounds__(256) void combine_kernel()
{
    int idx  = blockIdx.x * 256 + threadIdx.x;   // over BH_*T_*D_
    int d    = idx & 63;
    int rowi = idx >> 6;
    int t    = rowi & (T_-1);
    int bh   = rowi >> 12;
    int b = bh / H_, h = bh % H_;
    int p0 = g_undo[bh * TOTAL_ + t];
    int p1 = g_undo[bh * TOTAL_ + T_ + t];
    float l0 = g_slog[bh * TOTAL_ + p0];
    float l1 = g_slog[bh * TOTAL_ + p1];
    float mm = fmaxf(l0, l1);
    float w0 = __expf(l0 - mm), w1 = __expf(l1 - mm);
    float inv = 1.f / (w0 + w1);
    float o0 = g_so[((size_t)(bh * TOTAL_ + p0)) * D_ + d];
    float o1 = g_so[((size_t)(bh * TOTAL_ + p1)) * D_ + d];
    g_attn[((size_t)(b * T_ + t)) * HID_ + h * D_ + d] = (w0 * o0 + w1 * o1) * inv;
}

// ---------------- launcher ----------------
extern "C" void kernel_launch(void* const* d_in, const int* in_sizes, int n_in,
                              void* d_out, int out_size)
{
    const float* X    = (const float*)d_in[0];
    const float* mask = (const float*)d_in[1];
    const float* W_qk = (const float*)d_in[2];
    const float* W_v  = (const float*)d_in[3];
    const float* rot  = (const float*)d_in[4];
    const float* W_to = (const float*)d_in[5];
    const float* b_to = (const float*)d_in[6];
    const float* W_o  = (const float*)d_in[7];
    const float* b_o  = (const float*)d_in[8];
    float* out = (float*)d_out;

    dim3 gg(HID_ / 64, M_ / 128);   // (12, 128)

    sgemm_kernel<0,1><<<gg, 256>>>(X, W_qk, nullptr, nullptr);   // -> g_qk (merged heads)
    sgemm_kernel<0,2><<<gg, 256>>>(X, W_v,  nullptr, nullptr);   // -> g_v

    bucket_kernel<<<(BH_ * T_) / 8, 256>>>(rot);
    hist_kernel<<<BH_, 256>>>();
    scatter_kernel<<<dim3(NBTOT_, BH_), 256>>>();

    cudaFuncSetAttribute(attn_kernel, cudaFuncAttributeMaxDynamicSharedMemorySize, ATTN_SMEM_BYTES);
    attn_kernel<<<dim3(NCH_, BH_), 256, ATTN_SMEM_BYTES>>>(mask);

    combine_kernel<<<(BH_ * T_ * D_) / 256, 256>>>();

    sgemm_kernel<1,3><<<gg, 256>>>(nullptr, W_to, b_to, nullptr); // g_attn -> g_tmp
    sgemm_kernel<2,0><<<gg, 256>>>(nullptr, W_o,  b_o,  out);     // g_tmp  -> d_out
}